// round 15
// baseline (speedup 1.0000x reference)
#include <cuda_runtime.h>

#define BB 4
#define DD 128
#define HH 192
#define WW 192
#define HW (HH*WW)          // 36864
#define BHW (BB*HW)         // 147456
#define VOL ((size_t)DD*HW) // 4718592 per batch

#define DSPLIT 8
#define DCH (DD/DSPLIT)     // 16
#define NBLK (HW/256)       // 144 hw-blocks

// out layout: [x_2d | x_warp | y]
#define OFF_XWARP ((size_t)BHW)
#define OFF_Y     ((size_t)BHW + (size_t)BB*VOL)

__device__ float g_partial[DSPLIT * BHW];       // per-chunk partial sums
__device__ int   g_count[BB * NBLK];            // zero-init; self-resetting

// Guarded trilinear sample with border handling (zero outside).
__device__ __forceinline__ float guarded_sample(const float* __restrict__ vol,
                                                float gz, float gy, float gx) {
    float fz = floorf(gz), fy = floorf(gy), fx = floorf(gx);
    int iz = (int)fz, iy = (int)fy, ix = (int)fx;
    float rz = gz - fz, ry = gy - fy, rx = gx - fx;

    int iz1 = iz + 1, iy1 = iy + 1, ix1 = ix + 1;
    bool vz0 = (iz  >= 0) & (iz  < DD);
    bool vz1 = (iz1 >= 0) & (iz1 < DD);
    bool vy0 = (iy  >= 0) & (iy  < HH);
    bool vy1 = (iy1 >= 0) & (iy1 < HH);
    bool vx0 = (ix  >= 0) & (ix  < WW);
    bool vx1 = (ix1 >= 0) & (ix1 < WW);

    int z0c = min(max(iz , 0), DD-1);
    int z1c = min(max(iz1, 0), DD-1);
    int y0c = min(max(iy , 0), HH-1);
    int y1c = min(max(iy1, 0), HH-1);
    int x0c = min(max(ix , 0), WW-1);
    int x1c = min(max(ix1, 0), WW-1);

    const float* p00 = vol + (z0c * HH + y0c) * WW;
    const float* p01 = vol + (z0c * HH + y1c) * WW;
    const float* p10 = vol + (z1c * HH + y0c) * WW;
    const float* p11 = vol + (z1c * HH + y1c) * WW;

    float v000 = (vz0 & vy0 & vx0) ? p00[x0c] : 0.0f;
    float v001 = (vz0 & vy0 & vx1) ? p00[x1c] : 0.0f;
    float v010 = (vz0 & vy1 & vx0) ? p01[x0c] : 0.0f;
    float v011 = (vz0 & vy1 & vx1) ? p01[x1c] : 0.0f;
    float v100 = (vz1 & vy0 & vx0) ? p10[x0c] : 0.0f;
    float v101 = (vz1 & vy0 & vx1) ? p10[x1c] : 0.0f;
    float v110 = (vz1 & vy1 & vx0) ? p11[x0c] : 0.0f;
    float v111 = (vz1 & vy1 & vx1) ? p11[x1c] : 0.0f;

    float wx0 = 1.0f - rx, wy0 = 1.0f - ry, wz0 = 1.0f - rz;
    float a00 = fmaf(v001, rx, v000 * wx0);
    float a01 = fmaf(v011, rx, v010 * wx0);
    float a10 = fmaf(v101, rx, v100 * wx0);
    float a11 = fmaf(v111, rx, v110 * wx0);
    float b0  = fmaf(a01, ry, a00 * wy0);
    float b1  = fmaf(a11, ry, a10 * wy0);
    return fmaf(b1, rz, b0 * wz0);
}

// Shrink [lo,hi] (float d-range) to where g0 + s*d stays in
// (0.001, bound-1-0.001): both floor and floor+1 strictly interior.
__device__ __forceinline__ void axis_window(float g0, float s, float bound,
                                            float& lo, float& hi) {
    float upper = bound - 1.001f;
    if (fabsf(s) < 1e-6f) {
        if (!(g0 >= 0.001f && g0 <= upper)) { lo = 1e9f; hi = -1e9f; }
    } else {
        float inv = 1.0f / s;
        float a = (0.001f - g0) * inv;
        float b = (upper - g0) * inv;
        lo = fmaxf(lo, fminf(a, b));
        hi = fminf(hi, fmaxf(a, b));
    }
}

// floor/frac via the 2^23 trick: valid for 0 <= g < 2^23 (fast window only).
#define MAGIC 8388608.0f           // 2^23
#define MAGIC_BITS 0x4B000000

__device__ __forceinline__ void fast_floor(float g, int& i, float& r) {
    float t = __fadd_rz(g, MAGIC);           // RZ: truncation == floor (g>=0)
    i = __float_as_int(t) - MAGIC_BITS;      // mantissa low bits = floor(g)
    r = g - (t - MAGIC);                     // exact (Sterbenz)
}

__global__ __launch_bounds__(256, 6)
void warp_kernel(const float* __restrict__ x,  const float* __restrict__ y,
                 const float* __restrict__ rot0, const float* __restrict__ rot1,
                 const float* __restrict__ rot2, const float* __restrict__ tr1,
                 const float* __restrict__ tr2,  const float* __restrict__ cp,
                 float* __restrict__ out) {
    __shared__ float M[12];
    int b  = blockIdx.y;                              // 0..BB-1
    int c  = blockIdx.z;                              // 0..DSPLIT-1
    int hw = blockIdx.x * blockDim.x + threadIdx.x;   // 0..HW-1
    int idx = b * HW + hw;

    // y passthrough: chunk-0 CTAs cover exactly BHW threads. Issue first so
    // the load/store overlap the matrix setup + main loop.
    if (c == 0)
        out[OFF_Y + (size_t)idx] = y[idx];

    if (threadIdx.x == 0) {
        float az = rot0[b], ay = rot1[b], ax = rot2[b];
        float cz, szs, cy, sys, cx, sxs;
        sincosf(az, &szs, &cz);
        sincosf(ay, &sys, &cy);
        sincosf(ax, &sxs, &cx);
        float R0 = cz*cy;
        float R1 = -szs*cx + cz*sys*sxs;
        float R2 =  szs*sxs + cz*sys*cx;
        float R3 = szs*cy;
        float R4 =  cz*cx + szs*sys*sxs;
        float R5 = -cz*sxs + szs*sys*cx;
        float R6 = -sys;
        float R7 = cy*sxs;
        float R8 = cy*cx;
        float t1 = tr1[b] * (float)HH;
        float t2 = tr2[b] * (float)WW;
        float c0 = cp[b*3+0], c1 = cp[b*3+1], c2 = cp[b*3+2];
        M[0]=R0; M[1]=R1; M[2]=R2;
        M[3]=R3; M[4]=R4; M[5]=R5;
        M[6]=R6; M[7]=R7; M[8]=R8;
        M[9]  = 0.0f - (R0*c0 + R1*c1 + R2*c2) + c0;
        M[10] = t1   - (R3*c0 + R4*c1 + R5*c2) + c1;
        M[11] = t2   - (R6*c0 + R7*c1 + R8*c2) + c2;
    }
    __syncthreads();

    int h  = hw / WW;
    int w  = hw - h * WW;
    int d0 = c * DCH;
    int dend = d0 + DCH;

    float fh = (float)h, fw = (float)w;
    float gz0 = fmaf(M[1], fh, fmaf(M[2], fw, M[9]));
    float gy0 = fmaf(M[4], fh, fmaf(M[5], fw, M[10]));
    float gx0 = fmaf(M[7], fh, fmaf(M[8], fw, M[11]));
    float sz = M[0], sy = M[3], sx = M[6];

    const float* __restrict__ vol = x + (size_t)b * VOL;
    float* __restrict__ outw = out + OFF_XWARP + (size_t)b * VOL + (size_t)hw;

    // Exact interior d-window: intersection of three per-axis intervals.
    float wlo = (float)d0, whi = (float)(dend - 1);
    axis_window(gz0, sz, (float)DD, wlo, whi);
    axis_window(gy0, sy, (float)HH, wlo, whi);
    axis_window(gx0, sx, (float)WW, wlo, whi);

    int flo, fhi;
    if (wlo > whi) { flo = dend; fhi = dend; }
    else {
        flo = max(d0,   (int)ceilf(wlo));
        fhi = min(dend, (int)floorf(whi) + 1);
        if (flo > fhi) { flo = dend; fhi = dend; }
    }

    float sum = 0.0f;
    int j = d0;

    for (; j < flo; ++j) {   // pre-window guarded (boundary band only)
        float fd = (float)j;
        float val = guarded_sample(vol,
            fmaf(fd, sz, gz0), fmaf(fd, sy, gy0), fmaf(fd, sx, gx0));
        outw[(size_t)j * HW] = val;
        sum += val;
    }

    // Interior fast loop (R12 form — best measured): magic floor, 8
    // immediate-offset LDGs, FMA tree, coalesced store.
    #pragma unroll 4
    for (; j < fhi; ++j) {
        float fd = (float)j;
        float gz = fmaf(fd, sz, gz0);
        float gy = fmaf(fd, sy, gy0);
        float gx = fmaf(fd, sx, gx0);

        int iz, iy, ix;
        float rz, ry, rx;
        fast_floor(gz, iz, rz);
        fast_floor(gy, iy, ry);
        fast_floor(gx, ix, rx);

        const float* p = vol + iz * HW + iy * WW + ix;
        float v0 = p[0],       v1 = p[1];
        float v2 = p[WW],      v3 = p[WW + 1];
        float v4 = p[HW],      v5 = p[HW + 1];
        float v6 = p[HW + WW], v7 = p[HW + WW + 1];

        float wx0 = 1.0f - rx, wy0 = 1.0f - ry, wz0 = 1.0f - rz;
        float t00 = fmaf(v1, rx, v0 * wx0);
        float t01 = fmaf(v3, rx, v2 * wx0);
        float t10 = fmaf(v5, rx, v4 * wx0);
        float t11 = fmaf(v7, rx, v6 * wx0);
        float u0  = fmaf(t01, ry, t00 * wy0);
        float u1  = fmaf(t11, ry, t10 * wy0);
        float val = fmaf(u1,  rz, u0  * wz0);

        outw[(size_t)j * HW] = val;
        sum += val;
    }

    for (; j < dend; ++j) {  // post-window guarded
        float fd = (float)j;
        float val = guarded_sample(vol,
            fmaf(fd, sz, gz0), fmaf(fd, sy, gy0), fmaf(fd, sx, gx0));
        outw[(size_t)j * HW] = val;
        sum += val;
    }

    g_partial[(c * BB + b) * HW + hw] = sum;

    // ---- last-CTA reduction (threadFenceReduction pattern) ----
    __shared__ int s_last;
    __threadfence();                      // publish g_partial before counting
    __syncthreads();                      // all partials of this CTA written
    if (threadIdx.x == 0) {
        int gid = b * NBLK + blockIdx.x;
        int old = atomicAdd(&g_count[gid], 1);
        s_last = (old == DSPLIT - 1);
    }
    __syncthreads();

    if (s_last) {
        float s = 0.0f;
        #pragma unroll
        for (int cc = 0; cc < DSPLIT; ++cc)
            s += g_partial[(cc * BB + b) * HW + hw];
        out[idx] = s * (1.0f / (float)DD);
        __syncthreads();
        if (threadIdx.x == 0)
            g_count[b * NBLK + blockIdx.x] = 0;    // reset for next replay
    }
}

extern "C" void kernel_launch(void* const* d_in, const int* in_sizes, int n_in,
                              void* d_out, int out_size) {
    const float* x    = (const float*)d_in[0];
    const float* y    = (const float*)d_in[1];
    const float* rot0 = (const float*)d_in[2];
    const float* rot1 = (const float*)d_in[3];
    const float* rot2 = (const float*)d_in[4];
    const float* tr1  = (const float*)d_in[5];
    const float* tr2  = (const float*)d_in[6];
    const float* cp   = (const float*)d_in[7];
    float* out = (float*)d_out;

    dim3 grid(NBLK, BB, DSPLIT);
    warp_kernel<<<grid, 256>>>(x, y, rot0, rot1, rot2, tr1, tr2, cp, out);
}

// round 17
// speedup vs baseline: 1.1379x; 1.1379x over previous
#include <cuda_runtime.h>

#define BB 4
#define DD 128
#define HH 192
#define WW 192
#define HW (HH*WW)          // 36864
#define BHW (BB*HW)         // 147456
#define VOL ((size_t)DD*HW) // 4718592 per batch

#define DSPLIT 8
#define DCH (DD/DSPLIT)     // 16
#define NBLK (HW/256)       // 144 hw-blocks

// out layout: [x_2d | x_warp | y]
#define OFF_XWARP ((size_t)BHW)
#define OFF_Y     ((size_t)BHW + (size_t)BB*VOL)

__device__ float g_partial[DSPLIT * BHW];   // per-chunk partial sums

// Guarded trilinear sample with border handling (zero outside).
__device__ __forceinline__ float guarded_sample(const float* __restrict__ vol,
                                                float gz, float gy, float gx) {
    float fz = floorf(gz), fy = floorf(gy), fx = floorf(gx);
    int iz = (int)fz, iy = (int)fy, ix = (int)fx;
    float rz = gz - fz, ry = gy - fy, rx = gx - fx;

    int iz1 = iz + 1, iy1 = iy + 1, ix1 = ix + 1;
    bool vz0 = (iz  >= 0) & (iz  < DD);
    bool vz1 = (iz1 >= 0) & (iz1 < DD);
    bool vy0 = (iy  >= 0) & (iy  < HH);
    bool vy1 = (iy1 >= 0) & (iy1 < HH);
    bool vx0 = (ix  >= 0) & (ix  < WW);
    bool vx1 = (ix1 >= 0) & (ix1 < WW);

    int z0c = min(max(iz , 0), DD-1);
    int z1c = min(max(iz1, 0), DD-1);
    int y0c = min(max(iy , 0), HH-1);
    int y1c = min(max(iy1, 0), HH-1);
    int x0c = min(max(ix , 0), WW-1);
    int x1c = min(max(ix1, 0), WW-1);

    const float* p00 = vol + (z0c * HH + y0c) * WW;
    const float* p01 = vol + (z0c * HH + y1c) * WW;
    const float* p10 = vol + (z1c * HH + y0c) * WW;
    const float* p11 = vol + (z1c * HH + y1c) * WW;

    float v000 = (vz0 & vy0 & vx0) ? p00[x0c] : 0.0f;
    float v001 = (vz0 & vy0 & vx1) ? p00[x1c] : 0.0f;
    float v010 = (vz0 & vy1 & vx0) ? p01[x0c] : 0.0f;
    float v011 = (vz0 & vy1 & vx1) ? p01[x1c] : 0.0f;
    float v100 = (vz1 & vy0 & vx0) ? p10[x0c] : 0.0f;
    float v101 = (vz1 & vy0 & vx1) ? p10[x1c] : 0.0f;
    float v110 = (vz1 & vy1 & vx0) ? p11[x0c] : 0.0f;
    float v111 = (vz1 & vy1 & vx1) ? p11[x1c] : 0.0f;

    float wx0 = 1.0f - rx, wy0 = 1.0f - ry, wz0 = 1.0f - rz;
    float a00 = fmaf(v001, rx, v000 * wx0);
    float a01 = fmaf(v011, rx, v010 * wx0);
    float a10 = fmaf(v101, rx, v100 * wx0);
    float a11 = fmaf(v111, rx, v110 * wx0);
    float b0  = fmaf(a01, ry, a00 * wy0);
    float b1  = fmaf(a11, ry, a10 * wy0);
    return fmaf(b1, rz, b0 * wz0);
}

// Shrink [lo,hi] (float d-range) to where g0 + s*d stays in
// (0.001, bound-1-0.001): both floor and floor+1 strictly interior.
__device__ __forceinline__ void axis_window(float g0, float s, float bound,
                                            float& lo, float& hi) {
    float upper = bound - 1.001f;
    if (fabsf(s) < 1e-6f) {
        if (!(g0 >= 0.001f && g0 <= upper)) { lo = 1e9f; hi = -1e9f; }
    } else {
        float inv = 1.0f / s;
        float a = (0.001f - g0) * inv;
        float b = (upper - g0) * inv;
        lo = fmaxf(lo, fminf(a, b));
        hi = fminf(hi, fmaxf(a, b));
    }
}

// floor/frac via the 2^23 trick: valid for 0 <= g < 2^23 (fast window only).
#define MAGIC 8388608.0f           // 2^23
#define MAGIC_BITS 0x4B000000

__device__ __forceinline__ void fast_floor(float g, int& i, float& r) {
    float t = __fadd_rz(g, MAGIC);           // RZ: truncation == floor (g>=0)
    i = __float_as_int(t) - MAGIC_BITS;      // mantissa low bits = floor(g)
    r = g - (t - MAGIC);                     // exact (Sterbenz)
}

__global__ __launch_bounds__(256, 6)
void warp_kernel(const float* __restrict__ x,  const float* __restrict__ y,
                 const float* __restrict__ rot0, const float* __restrict__ rot1,
                 const float* __restrict__ rot2, const float* __restrict__ tr1,
                 const float* __restrict__ tr2,  const float* __restrict__ cp,
                 float* __restrict__ out) {
    __shared__ float M[12];
    int b  = blockIdx.y;                              // 0..BB-1
    int c  = blockIdx.z;                              // 0..DSPLIT-1
    int hw = blockIdx.x * blockDim.x + threadIdx.x;   // 0..HW-1

    // y passthrough: chunk-0 CTAs cover exactly BHW threads; overlapped
    // with everything else (no fence, no tail work).
    if (c == 0) {
        int idx = b * HW + hw;
        out[OFF_Y + (size_t)idx] = y[idx];
    }

    if (threadIdx.x == 0) {
        float az = rot0[b], ay = rot1[b], ax = rot2[b];
        float cz, szs, cy, sys, cx, sxs;
        sincosf(az, &szs, &cz);
        sincosf(ay, &sys, &cy);
        sincosf(ax, &sxs, &cx);
        float R0 = cz*cy;
        float R1 = -szs*cx + cz*sys*sxs;
        float R2 =  szs*sxs + cz*sys*cx;
        float R3 = szs*cy;
        float R4 =  cz*cx + szs*sys*sxs;
        float R5 = -cz*sxs + szs*sys*cx;
        float R6 = -sys;
        float R7 = cy*sxs;
        float R8 = cy*cx;
        float t1 = tr1[b] * (float)HH;
        float t2 = tr2[b] * (float)WW;
        float c0 = cp[b*3+0], c1 = cp[b*3+1], c2 = cp[b*3+2];
        M[0]=R0; M[1]=R1; M[2]=R2;
        M[3]=R3; M[4]=R4; M[5]=R5;
        M[6]=R6; M[7]=R7; M[8]=R8;
        M[9]  = 0.0f - (R0*c0 + R1*c1 + R2*c2) + c0;
        M[10] = t1   - (R3*c0 + R4*c1 + R5*c2) + c1;
        M[11] = t2   - (R6*c0 + R7*c1 + R8*c2) + c2;
    }
    __syncthreads();

    int h  = hw / WW;
    int w  = hw - h * WW;
    int d0 = c * DCH;
    int dend = d0 + DCH;

    float fh = (float)h, fw = (float)w;
    float gz0 = fmaf(M[1], fh, fmaf(M[2], fw, M[9]));
    float gy0 = fmaf(M[4], fh, fmaf(M[5], fw, M[10]));
    float gx0 = fmaf(M[7], fh, fmaf(M[8], fw, M[11]));
    float sz = M[0], sy = M[3], sx = M[6];

    const float* __restrict__ vol = x + (size_t)b * VOL;
    float* __restrict__ outw = out + OFF_XWARP + (size_t)b * VOL + (size_t)hw;

    // Exact interior d-window: intersection of three per-axis intervals.
    float wlo = (float)d0, whi = (float)(dend - 1);
    axis_window(gz0, sz, (float)DD, wlo, whi);
    axis_window(gy0, sy, (float)HH, wlo, whi);
    axis_window(gx0, sx, (float)WW, wlo, whi);

    int flo, fhi;
    if (wlo > whi) { flo = dend; fhi = dend; }
    else {
        flo = max(d0,   (int)ceilf(wlo));
        fhi = min(dend, (int)floorf(whi) + 1);
        if (flo > fhi) { flo = dend; fhi = dend; }
    }

    float sum = 0.0f;
    int j = d0;

    for (; j < flo; ++j) {   // pre-window guarded (boundary band only)
        float fd = (float)j;
        float val = guarded_sample(vol,
            fmaf(fd, sz, gz0), fmaf(fd, sy, gy0), fmaf(fd, sx, gx0));
        outw[(size_t)j * HW] = val;
        sum += val;
    }

    // Interior fast loop (R12 form — best measured): magic floor, 8
    // immediate-offset LDGs, FMA tree, coalesced store.
    #pragma unroll 4
    for (; j < fhi; ++j) {
        float fd = (float)j;
        float gz = fmaf(fd, sz, gz0);
        float gy = fmaf(fd, sy, gy0);
        float gx = fmaf(fd, sx, gx0);

        int iz, iy, ix;
        float rz, ry, rx;
        fast_floor(gz, iz, rz);
        fast_floor(gy, iy, ry);
        fast_floor(gx, ix, rx);

        const float* p = vol + iz * HW + iy * WW + ix;
        float v0 = p[0],       v1 = p[1];
        float v2 = p[WW],      v3 = p[WW + 1];
        float v4 = p[HW],      v5 = p[HW + 1];
        float v6 = p[HW + WW], v7 = p[HW + WW + 1];

        float wx0 = 1.0f - rx, wy0 = 1.0f - ry, wz0 = 1.0f - rz;
        float t00 = fmaf(v1, rx, v0 * wx0);
        float t01 = fmaf(v3, rx, v2 * wx0);
        float t10 = fmaf(v5, rx, v4 * wx0);
        float t11 = fmaf(v7, rx, v6 * wx0);
        float u0  = fmaf(t01, ry, t00 * wy0);
        float u1  = fmaf(t11, ry, t10 * wy0);
        float val = fmaf(u1,  rz, u0  * wz0);

        outw[(size_t)j * HW] = val;
        sum += val;
    }

    for (; j < dend; ++j) {  // post-window guarded
        float fd = (float)j;
        float val = guarded_sample(vol,
            fmaf(fd, sz, gz0), fmaf(fd, sy, gy0), fmaf(fd, sx, gx0));
        outw[(size_t)j * HW] = val;
        sum += val;
    }

    g_partial[(c * BB + b) * HW + hw] = sum;
}

// x_2d = mean of partials (float4).
__global__ __launch_bounds__(128)
void reduce_kernel(float* __restrict__ out) {
    int i = blockIdx.x * blockDim.x + threadIdx.x;   // 0..BHW/4-1
    if (i >= BHW / 4) return;
    int i4 = i * 4;
    int b  = i4 / HW;           // HW % 4 == 0 -> same b for all 4 lanes
    int hw = i4 - b * HW;

    float4 s = make_float4(0.f, 0.f, 0.f, 0.f);
    #pragma unroll
    for (int c = 0; c < DSPLIT; ++c) {
        const float4 p = *(const float4*)&g_partial[(c * BB + b) * HW + hw];
        s.x += p.x; s.y += p.y; s.z += p.z; s.w += p.w;
    }
    const float inv = 1.0f / (float)DD;
    s.x *= inv; s.y *= inv; s.z *= inv; s.w *= inv;
    *(float4*)&out[i4] = s;
}

extern "C" void kernel_launch(void* const* d_in, const int* in_sizes, int n_in,
                              void* d_out, int out_size) {
    const float* x    = (const float*)d_in[0];
    const float* y    = (const float*)d_in[1];
    const float* rot0 = (const float*)d_in[2];
    const float* rot1 = (const float*)d_in[3];
    const float* rot2 = (const float*)d_in[4];
    const float* tr1  = (const float*)d_in[5];
    const float* tr2  = (const float*)d_in[6];
    const float* cp   = (const float*)d_in[7];
    float* out = (float*)d_out;

    dim3 grid(NBLK, BB, DSPLIT);
    warp_kernel<<<grid, 256>>>(x, y, rot0, rot1, rot2, tr1, tr2, cp, out);
    reduce_kernel<<<(BHW / 4 + 127) / 128, 128>>>(out);
}